// round 11
// baseline (speedup 1.0000x reference)
#include <cuda_runtime.h>

typedef unsigned long long u64;

__device__ __forceinline__ u64 pk2(float lo, float hi) {
    u64 r; asm("mov.b64 %0,{%1,%2};" : "=l"(r) : "f"(lo), "f"(hi)); return r;
}
__device__ __forceinline__ u64 fma2(u64 a, u64 b, u64 c) {
    u64 d; asm("fma.rn.f32x2 %0,%1,%2,%3;" : "=l"(d) : "l"(a), "l"(b), "l"(c)); return d;
}
__device__ __forceinline__ float sum2(u64 a) {
    float lo, hi; asm("mov.b64 {%0,%1},%2;" : "=f"(lo), "=f"(hi) : "l"(a)); return lo + hi;
}
__device__ __forceinline__ unsigned smem_u32(const void* p) {
    unsigned a;
    asm("{ .reg .u64 t; cvta.to.shared.u64 t, %1; cvt.u32.u64 %0, t; }" : "=r"(a) : "l"(p));
    return a;
}
__device__ __forceinline__ void cp_async16(unsigned s, const void* g) {
    asm volatile("cp.async.cg.shared.global [%0], [%1], 16;" :: "r"(s), "l"(g));
}

// Scratch + sync flags (self-resetting each launch -> deterministic)
__device__ float g_n1[2048 * 8];     // n1[row][k]
__device__ float g_n2T[6 * 2048];    // n2 transposed [k][row]
__device__ int   g_done;             // gcn blocks completed (0..256)
__device__ int   g_adjdone;          // adj blocks completed (0..2048)

// ---------------------------------------------------------------------------
// Fused kernel: blocks 0..255 = GCN role (t -> gcn -> out, n1/n2);
//               blocks 256..2303 = ADJ role (wa-term + e-term, then wait
//               for n1/n2 flags and fold).
// True intra-launch overlap: gcn (LDS-bound) and adj (DRAM-bound) co-reside.
// ---------------------------------------------------------------------------
__global__ void __launch_bounds__(256, 5) k_fused(const float* __restrict__ x,
                                                  const float* __restrict__ wa,
                                                  const float* __restrict__ e,
                                                  const float* __restrict__ Ww,
                                                  const float* __restrict__ Wb,
                                                  const float* __restrict__ Wx_w,
                                                  const float* __restrict__ Wx_b,
                                                  const float* __restrict__ Wxx,
                                                  const float* __restrict__ Wxxb,
                                                  float* __restrict__ out,
                                                  float* __restrict__ adj_out) {
    __shared__ __align__(16) float smem[10752];   // 42KB, overlaid per role
    int tid = threadIdx.x;

    if (blockIdx.x < 256) {
        // ==================== GCN role ====================
        float* pool = smem;            // 8192: x tiles / w tiles / partials
        float* a_s  = smem + 8192;     // [2][256]
        float* t_s  = smem + 8704;     // 1024
        float* g_s  = smem + 9728;     // 1024
        int b    = blockIdx.x >> 5;
        int i0   = (blockIdx.x & 31) << 3;
        int lane = tid & 127;
        int half = tid >> 7;
        int r0   = blockIdx.x * 8;
        const float inv6 = 1.0f / 6.0f;

        // ---- Phase A: t = mean_h(wa) @ x (halves split j) ----
        u64 acc2[8];
        #pragma unroll
        for (int ii = 0; ii < 8; ii++) acc2[ii] = 0ull;

        for (int jt = 0; jt < 4; jt++) {
            int j0 = half * 128 + jt * 32;
            const float4* xs = (const float4*)(x + ((long)b * 256 + j0) * 128);
            float4*       xd = (float4*)(pool + half * 4096);
            #pragma unroll
            for (int idx = lane; idx < 1024; idx += 128) xd[idx] = xs[idx];
            #pragma unroll
            for (int ent = lane; ent < 256; ent += 128) {
                int ii = ent >> 5, jj = ent & 31;
                float s = 0.0f;
                #pragma unroll
                for (int h = 0; h < 6; h++)
                    s += wa[(((long)(b * 6 + h) * 256) + i0 + ii) * 256 + j0 + jj];
                a_s[half * 256 + ent] = s * inv6;
            }
            __syncthreads();
            const float* xh = pool + half * 4096;
            const float* ah = a_s + half * 256;
            #pragma unroll
            for (int jj = 0; jj < 32; jj += 2) {
                u64 xp = pk2(xh[jj * 128 + lane], xh[(jj + 1) * 128 + lane]);
                #pragma unroll
                for (int ii = 0; ii < 8; ii++)
                    acc2[ii] = fma2(*(const u64*)&ah[ii * 32 + jj], xp, acc2[ii]);
            }
            __syncthreads();
        }
        #pragma unroll
        for (int ii = 0; ii < 8; ii++) pool[half * 1024 + ii * 128 + lane] = sum2(acc2[ii]);
        __syncthreads();
        #pragma unroll
        for (int idx = tid; idx < 1024; idx += 256) t_s[idx] = pool[idx] + pool[1024 + idx];
        __syncthreads();

        // ---- Phase B: gcn = relu(t @ Ww^T + b), halves split rows ----
        u64 b2[4];
        #pragma unroll
        for (int r = 0; r < 4; r++) b2[r] = 0ull;
        for (int kt = 0; kt < 4; kt++) {
            int k0 = kt * 32;
            #pragma unroll
            for (int idx = tid; idx < 4096; idx += 256) {
                int d = idx >> 5, c = idx & 31;
                pool[c * 129 + d] = Ww[d * 128 + k0 + c];
            }
            __syncthreads();
            #pragma unroll
            for (int kk = 0; kk < 32; kk += 2) {
                u64 wp = pk2(pool[kk * 129 + lane], pool[(kk + 1) * 129 + lane]);
                #pragma unroll
                for (int r = 0; r < 4; r++)
                    b2[r] = fma2(*(const u64*)&t_s[(half * 4 + r) * 128 + k0 + kk], wp, b2[r]);
            }
            __syncthreads();
        }
        float bb = Wb[lane];
        #pragma unroll
        for (int r = 0; r < 4; r++)
            g_s[(half * 4 + r) * 128 + lane] = fmaxf(sum2(b2[r]) + bb, 0.0f);
        __syncthreads();

        // ---- Phase C: out = gcn @ Wxx^T + b ----
        u64 o2[4];
        #pragma unroll
        for (int r = 0; r < 4; r++) o2[r] = 0ull;
        for (int kt = 0; kt < 4; kt++) {
            int k0 = kt * 32;
            #pragma unroll
            for (int idx = tid; idx < 4096; idx += 256) {
                int d = idx >> 5, c = idx & 31;
                pool[c * 129 + d] = Wxx[d * 128 + k0 + c];
            }
            __syncthreads();
            #pragma unroll
            for (int kk = 0; kk < 32; kk += 2) {
                u64 wp = pk2(pool[kk * 129 + lane], pool[(kk + 1) * 129 + lane]);
                #pragma unroll
                for (int r = 0; r < 4; r++)
                    o2[r] = fma2(*(const u64*)&g_s[(half * 4 + r) * 128 + k0 + kk], wp, o2[r]);
            }
            __syncthreads();
        }
        float ob = Wxxb[lane];
        #pragma unroll
        for (int r = 0; r < 4; r++)
            out[(long)(r0 + half * 4 + r) * 128 + lane] = sum2(o2[r]) + ob;

        // ---- Phase D: n1/n2 (96 dots of length 128) ----
        if (tid < 96) {
            int sel = tid >= 48;
            int q   = tid - sel * 48;
            int r   = q / 6, k = q % 6;
            const float* gp = g_s + r * 128;
            const float* w  = Wx_w + k * 294 + 6 + sel * 128;
            u64 s = 0ull;
            #pragma unroll 8
            for (int d = 0; d < 128; d += 2)
                s = fma2(*(const u64*)&gp[d], pk2(__ldg(&w[d]), __ldg(&w[d + 1])), s);
            float v = sum2(s);
            if (sel == 0) g_n1[(r0 + r) * 8 + k]   = v;
            else          g_n2T[k * 2048 + r0 + r] = v;
        }
        __threadfence();
        __syncthreads();
        if (tid == 0) atomicAdd(&g_done, 1);    // release: n1/n2 visible

    } else {
        // ==================== ADJ role ====================
        float* e_s   = smem;            // [j][36], 9216 floats
        float* Wa_s  = smem + 9216;     // 40
        float* We_s  = smem + 9280;     // 200
        float* n1b_s = smem + 9984;     // 16
        int abid = blockIdx.x - 256;
        int b    = abid >> 8;
        int i    = abid & 255;

        const float4* e4 = (const float4*)(e + (((long)b * 256 + i) * 256) * 32);
        #pragma unroll
        for (int it = 0; it < 8; it++) {
            int idx = tid + it * 256;
            unsigned dst = smem_u32(&e_s[(idx >> 3) * 36 + (idx & 7) * 4]);
            cp_async16(dst, &e4[idx]);
        }
        asm volatile("cp.async.commit_group;" ::: "memory");

        float wv[6];
        #pragma unroll
        for (int h = 0; h < 6; h++)
            wv[h] = wa[(((long)(b * 6 + h) * 256) + i) * 256 + tid];
        if (tid < 36) Wa_s[tid] = Wx_w[(tid / 6) * 294 + tid % 6];
        if (tid >= 64 && tid < 256) {
            int t = tid - 64;
            We_s[t] = Wx_w[(t >> 5) * 294 + 262 + (t & 31)];
        }
        if (tid >= 48 && tid < 54) n1b_s[8 + tid - 48] = Wx_b[tid - 48];

        asm volatile("cp.async.wait_group 0;" ::: "memory");
        __syncthreads();

        u64 acc2[6];
        #pragma unroll
        for (int k = 0; k < 6; k++) acc2[k] = 0ull;

        u64 wp0 = pk2(wv[0], wv[1]), wp1 = pk2(wv[2], wv[3]), wp2 = pk2(wv[4], wv[5]);
        #pragma unroll
        for (int k = 0; k < 6; k++) {
            acc2[k] = fma2(*(const u64*)&Wa_s[k * 6 + 0], wp0, acc2[k]);
            acc2[k] = fma2(*(const u64*)&Wa_s[k * 6 + 2], wp1, acc2[k]);
            acc2[k] = fma2(*(const u64*)&Wa_s[k * 6 + 4], wp2, acc2[k]);
        }

        const float4* ep = (const float4*)&e_s[tid * 36];
        #pragma unroll
        for (int q = 0; q < 8; q++) {
            float4 w = ep[q];
            u64 ev0 = pk2(w.x, w.y);
            u64 ev1 = pk2(w.z, w.w);
            #pragma unroll
            for (int k = 0; k < 6; k++) {
                acc2[k] = fma2(ev0, *(const u64*)&We_s[k * 32 + q * 4 + 0], acc2[k]);
                acc2[k] = fma2(ev1, *(const u64*)&We_s[k * 32 + q * 4 + 2], acc2[k]);
            }
        }

        // ---- wait for the 256 gcn blocks (heavy phase already done) ----
        if (tid == 0) {
            while (atomicAdd(&g_done, 0) < 256) __nanosleep(256);
            __threadfence();   // acquire
        }
        __syncthreads();

        if (tid < 6) n1b_s[tid] = g_n1[((long)b * 256 + i) * 8 + tid];
        float n2v[6];
        #pragma unroll
        for (int k = 0; k < 6; k++) n2v[k] = g_n2T[k * 2048 + b * 256 + tid];
        __syncthreads();

        long ob = ((long)(b * 6) * 65536) + (long)i * 256 + tid;
        #pragma unroll
        for (int k = 0; k < 6; k++)
            adj_out[ob + (long)k * 65536] = sum2(acc2[k]) + n1b_s[k] + n1b_s[8 + k] + n2v[k];

        // ---- self-reset for graph replay determinism ----
        __threadfence();
        if (tid == 0) {
            int v = atomicAdd(&g_adjdone, 1);
            if (v == 2047) { g_done = 0; g_adjdone = 0; }
        }
    }
}

// ---------------------------------------------------------------------------
extern "C" void kernel_launch(void* const* d_in, const int* in_sizes, int n_in,
                              void* d_out, int out_size) {
    const float* x     = (const float*)d_in[0];
    const float* wa    = (const float*)d_in[1];
    const float* e     = (const float*)d_in[2];
    const float* W_w   = (const float*)d_in[3];
    const float* W_b   = (const float*)d_in[4];
    const float* Wx_w  = (const float*)d_in[5];
    const float* Wx_b  = (const float*)d_in[6];
    const float* Wxx_w = (const float*)d_in[7];
    const float* Wxx_b = (const float*)d_in[8];

    float* out     = (float*)d_out;            // (B,L,D)
    float* adj_out = out + 8 * 256 * 128;      // (B,H,L,L)

    k_fused<<<2304, 256>>>(x, wa, e, W_w, W_b, Wx_w, Wx_b, Wxx_w, Wxx_b,
                           out, adj_out);
}

// round 12
// speedup vs baseline: 1.2200x; 1.2200x over previous
#include <cuda_runtime.h>

typedef unsigned long long u64;

__device__ __forceinline__ u64 pk2(float lo, float hi) {
    u64 r; asm("mov.b64 %0,{%1,%2};" : "=l"(r) : "f"(lo), "f"(hi)); return r;
}
__device__ __forceinline__ u64 fma2(u64 a, u64 b, u64 c) {
    u64 d; asm("fma.rn.f32x2 %0,%1,%2,%3;" : "=l"(d) : "l"(a), "l"(b), "l"(c)); return d;
}
__device__ __forceinline__ float sum2(u64 a) {
    float lo, hi; asm("mov.b64 {%0,%1},%2;" : "=f"(lo), "=f"(hi) : "l"(a)); return lo + hi;
}
__device__ __forceinline__ unsigned smem_u32(const void* p) {
    unsigned a;
    asm("{ .reg .u64 t; cvta.to.shared.u64 t, %1; cvt.u32.u64 %0, t; }" : "=r"(a) : "l"(p));
    return a;
}
__device__ __forceinline__ void cp_async16(unsigned s, const void* g) {
    asm volatile("cp.async.cg.shared.global [%0], [%1], 16;" :: "r"(s), "l"(g));
}

// Scratch (no sync flags — no inter-block dependencies anywhere)
__device__ float g_n1[2048 * 8];     // n1[row][k]
__device__ float g_n2T[6 * 2048];    // n2 transposed [k][row]

// ---------------------------------------------------------------------------
// Fused kernel, NO inter-block waits:
//   blocks 0..255    = GCN role (t -> gcn -> out, n1/n2 to scratch)
//   blocks 256..2303 = ADJ role (wa-term + e-term + bias -> adj_out PARTIAL)
// gcn ids lowest -> resident from wave 1; adj streams around them.
// The n1/n2 fold happens in the tiny k_add pass afterward.
// ---------------------------------------------------------------------------
__global__ void __launch_bounds__(256, 5) k_fused(const float* __restrict__ x,
                                                  const float* __restrict__ wa,
                                                  const float* __restrict__ e,
                                                  const float* __restrict__ Ww,
                                                  const float* __restrict__ Wb,
                                                  const float* __restrict__ Wx_w,
                                                  const float* __restrict__ Wx_b,
                                                  const float* __restrict__ Wxx,
                                                  const float* __restrict__ Wxxb,
                                                  float* __restrict__ out,
                                                  float* __restrict__ adj_out) {
    __shared__ __align__(16) float smem[10752];   // 42KB, overlaid per role
    int tid = threadIdx.x;

    if (blockIdx.x < 256) {
        // ==================== GCN role ====================
        float* pool = smem;            // 8192: x tiles / w tiles / partials
        float* a_s  = smem + 8192;     // [2][256]
        float* t_s  = smem + 8704;     // 1024
        float* g_s  = smem + 9728;     // 1024
        int b    = blockIdx.x >> 5;
        int i0   = (blockIdx.x & 31) << 3;
        int lane = tid & 127;
        int half = tid >> 7;
        int r0   = blockIdx.x * 8;
        const float inv6 = 1.0f / 6.0f;

        // ---- Phase A: t = mean_h(wa) @ x (halves split j) ----
        u64 acc2[8];
        #pragma unroll
        for (int ii = 0; ii < 8; ii++) acc2[ii] = 0ull;

        for (int jt = 0; jt < 4; jt++) {
            int j0 = half * 128 + jt * 32;
            const float4* xs = (const float4*)(x + ((long)b * 256 + j0) * 128);
            float4*       xd = (float4*)(pool + half * 4096);
            #pragma unroll
            for (int idx = lane; idx < 1024; idx += 128) xd[idx] = xs[idx];
            #pragma unroll
            for (int ent = lane; ent < 256; ent += 128) {
                int ii = ent >> 5, jj = ent & 31;
                float s = 0.0f;
                #pragma unroll
                for (int h = 0; h < 6; h++)
                    s += wa[(((long)(b * 6 + h) * 256) + i0 + ii) * 256 + j0 + jj];
                a_s[half * 256 + ent] = s * inv6;
            }
            __syncthreads();
            const float* xh = pool + half * 4096;
            const float* ah = a_s + half * 256;
            #pragma unroll
            for (int jj = 0; jj < 32; jj += 2) {
                u64 xp = pk2(xh[jj * 128 + lane], xh[(jj + 1) * 128 + lane]);
                #pragma unroll
                for (int ii = 0; ii < 8; ii++)
                    acc2[ii] = fma2(*(const u64*)&ah[ii * 32 + jj], xp, acc2[ii]);
            }
            __syncthreads();
        }
        #pragma unroll
        for (int ii = 0; ii < 8; ii++) pool[half * 1024 + ii * 128 + lane] = sum2(acc2[ii]);
        __syncthreads();
        #pragma unroll
        for (int idx = tid; idx < 1024; idx += 256) t_s[idx] = pool[idx] + pool[1024 + idx];
        __syncthreads();

        // ---- Phase B: gcn = relu(t @ Ww^T + b), halves split rows ----
        u64 b2[4];
        #pragma unroll
        for (int r = 0; r < 4; r++) b2[r] = 0ull;
        for (int kt = 0; kt < 4; kt++) {
            int k0 = kt * 32;
            #pragma unroll
            for (int idx = tid; idx < 4096; idx += 256) {
                int d = idx >> 5, c = idx & 31;
                pool[c * 129 + d] = Ww[d * 128 + k0 + c];
            }
            __syncthreads();
            #pragma unroll
            for (int kk = 0; kk < 32; kk += 2) {
                u64 wp = pk2(pool[kk * 129 + lane], pool[(kk + 1) * 129 + lane]);
                #pragma unroll
                for (int r = 0; r < 4; r++)
                    b2[r] = fma2(*(const u64*)&t_s[(half * 4 + r) * 128 + k0 + kk], wp, b2[r]);
            }
            __syncthreads();
        }
        float bb = Wb[lane];
        #pragma unroll
        for (int r = 0; r < 4; r++)
            g_s[(half * 4 + r) * 128 + lane] = fmaxf(sum2(b2[r]) + bb, 0.0f);
        __syncthreads();

        // ---- Phase C: out = gcn @ Wxx^T + b ----
        u64 o2[4];
        #pragma unroll
        for (int r = 0; r < 4; r++) o2[r] = 0ull;
        for (int kt = 0; kt < 4; kt++) {
            int k0 = kt * 32;
            #pragma unroll
            for (int idx = tid; idx < 4096; idx += 256) {
                int d = idx >> 5, c = idx & 31;
                pool[c * 129 + d] = Wxx[d * 128 + k0 + c];
            }
            __syncthreads();
            #pragma unroll
            for (int kk = 0; kk < 32; kk += 2) {
                u64 wp = pk2(pool[kk * 129 + lane], pool[(kk + 1) * 129 + lane]);
                #pragma unroll
                for (int r = 0; r < 4; r++)
                    o2[r] = fma2(*(const u64*)&g_s[(half * 4 + r) * 128 + k0 + kk], wp, o2[r]);
            }
            __syncthreads();
        }
        float ob = Wxxb[lane];
        #pragma unroll
        for (int r = 0; r < 4; r++)
            out[(long)(r0 + half * 4 + r) * 128 + lane] = sum2(o2[r]) + ob;

        // ---- Phase D: n1/n2 (96 dots of length 128) ----
        if (tid < 96) {
            int sel = tid >= 48;
            int q   = tid - sel * 48;
            int r   = q / 6, k = q % 6;
            const float* gp = g_s + r * 128;
            const float* w  = Wx_w + k * 294 + 6 + sel * 128;
            u64 s = 0ull;
            #pragma unroll 8
            for (int d = 0; d < 128; d += 2)
                s = fma2(*(const u64*)&gp[d], pk2(__ldg(&w[d]), __ldg(&w[d + 1])), s);
            float v = sum2(s);
            if (sel == 0) g_n1[(r0 + r) * 8 + k]   = v;
            else          g_n2T[k * 2048 + r0 + r] = v;
        }

    } else {
        // ==================== ADJ role (partial, no waits) ====================
        float* e_s    = smem;            // [j][36], 9216 floats
        float* Wa_s   = smem + 9216;     // 40
        float* We_s   = smem + 9280;     // 200
        float* bias_s = smem + 9984;     // 8
        int abid = blockIdx.x - 256;
        int b    = abid >> 8;
        int i    = abid & 255;

        const float4* e4 = (const float4*)(e + (((long)b * 256 + i) * 256) * 32);
        #pragma unroll
        for (int it = 0; it < 8; it++) {
            int idx = tid + it * 256;
            unsigned dst = smem_u32(&e_s[(idx >> 3) * 36 + (idx & 7) * 4]);
            cp_async16(dst, &e4[idx]);
        }
        asm volatile("cp.async.commit_group;" ::: "memory");

        float wv[6];
        #pragma unroll
        for (int h = 0; h < 6; h++)
            wv[h] = wa[(((long)(b * 6 + h) * 256) + i) * 256 + tid];
        if (tid < 36) Wa_s[tid] = Wx_w[(tid / 6) * 294 + tid % 6];
        if (tid >= 64 && tid < 256) {
            int t = tid - 64;
            We_s[t] = Wx_w[(t >> 5) * 294 + 262 + (t & 31)];
        }
        if (tid >= 48 && tid < 54) bias_s[tid - 48] = Wx_b[tid - 48];

        asm volatile("cp.async.wait_group 0;" ::: "memory");
        __syncthreads();

        u64 acc2[6];
        #pragma unroll
        for (int k = 0; k < 6; k++) acc2[k] = 0ull;

        u64 wp0 = pk2(wv[0], wv[1]), wp1 = pk2(wv[2], wv[3]), wp2 = pk2(wv[4], wv[5]);
        #pragma unroll
        for (int k = 0; k < 6; k++) {
            acc2[k] = fma2(*(const u64*)&Wa_s[k * 6 + 0], wp0, acc2[k]);
            acc2[k] = fma2(*(const u64*)&Wa_s[k * 6 + 2], wp1, acc2[k]);
            acc2[k] = fma2(*(const u64*)&Wa_s[k * 6 + 4], wp2, acc2[k]);
        }

        const float4* ep = (const float4*)&e_s[tid * 36];
        #pragma unroll
        for (int q = 0; q < 8; q++) {
            float4 w = ep[q];
            u64 ev0 = pk2(w.x, w.y);
            u64 ev1 = pk2(w.z, w.w);
            #pragma unroll
            for (int k = 0; k < 6; k++) {
                acc2[k] = fma2(ev0, *(const u64*)&We_s[k * 32 + q * 4 + 0], acc2[k]);
                acc2[k] = fma2(ev1, *(const u64*)&We_s[k * 32 + q * 4 + 2], acc2[k]);
            }
        }

        long ob = ((long)(b * 6) * 65536) + (long)i * 256 + tid;
        #pragma unroll
        for (int k = 0; k < 6; k++)
            adj_out[ob + (long)k * 65536] = sum2(acc2[k]) + bias_s[k];
    }
}

// ---------------------------------------------------------------------------
// adj_out[b,k,i,j] += n1[b,i,k] + n2[b,j,k]   (streaming float4 RMW, ~4us)
// grid = B*6*64 = 3072 blocks, 256 threads; block = (b,k, 4 i-rows)
// ---------------------------------------------------------------------------
__global__ void __launch_bounds__(256) k_add(float* __restrict__ adj_out) {
    int bid = blockIdx.x;
    int bk  = bid >> 6;               // b*6+k
    int iq  = bid & 63;
    int b   = bk / 6, k = bk - b * 6;
    int tid = threadIdx.x;
    int ir  = tid >> 6;               // 0..3
    int jj  = (tid & 63) << 2;
    int i   = iq * 4 + ir;

    float  n1v = g_n1[((b * 256 + i) * 8) + k];
    float4 n2v = *(const float4*)&g_n2T[k * 2048 + b * 256 + jj];

    long off = ((long)(b * 6 + k) << 16) + i * 256 + jj;
    float4 v = *(float4*)&adj_out[off];
    v.x += n1v + n2v.x;
    v.y += n1v + n2v.y;
    v.z += n1v + n2v.z;
    v.w += n1v + n2v.w;
    *(float4*)&adj_out[off] = v;
}

// ---------------------------------------------------------------------------
extern "C" void kernel_launch(void* const* d_in, const int* in_sizes, int n_in,
                              void* d_out, int out_size) {
    const float* x     = (const float*)d_in[0];
    const float* wa    = (const float*)d_in[1];
    const float* e     = (const float*)d_in[2];
    const float* W_w   = (const float*)d_in[3];
    const float* W_b   = (const float*)d_in[4];
    const float* Wx_w  = (const float*)d_in[5];
    const float* Wx_b  = (const float*)d_in[6];
    const float* Wxx_w = (const float*)d_in[7];
    const float* Wxx_b = (const float*)d_in[8];

    float* out     = (float*)d_out;            // (B,L,D)
    float* adj_out = out + 8 * 256 * 128;      // (B,H,L,L)

    k_fused<<<2304, 256>>>(x, wa, e, W_w, W_b, Wx_w, Wx_b, Wxx_w, Wxx_b,
                           out, adj_out);
    k_add<<<3072, 256>>>(adj_out);
}